// round 6
// baseline (speedup 1.0000x reference)
#include <cuda_runtime.h>
#include <cuda_bf16.h>
#include <cstdint>

// HardNetLoss, screen-then-fix v2:
//   int8 screening GEMM (ldmatrix + 64x64 warp tiles) + coalesced bf16 dump,
//   scan S~ for candidates within margin of screened row/col maxes,
//   exact fp32 dot fix, exact diagonal, tiny finish.

#define CNT 8192
#define KDIM 256
#define EPSV 1e-6f
#define MARGIN_C 0.05f

#define TSTRIDE 272
#define TILE_BYTES (128 * TSTRIDE)        // 34816
#define SM_SROW (2 * TILE_BYTES)
#define SM_SCOL (2 * TILE_BYTES + 512)
#define SM_TOTAL (2 * TILE_BYTES + 1024)  // 70656

#define LIST_CAP 2048
#define RPB 8

__device__ unsigned char g_q[2 * CNT * KDIM];
__device__ __nv_bfloat16 g_S[(size_t)CNT * CNT];
__device__ unsigned g_srow[CNT], g_scol[CNT];
__device__ unsigned g_erow[CNT], g_ecol[CNT];
__device__ float    g_diag[CNT];
__device__ float    g_partial[CNT / 256];
__device__ unsigned g_maxabs;
__device__ float    g_scale, g_inv2;

__device__ __forceinline__ unsigned encf(float f) {
    unsigned u = __float_as_uint(f);
    return (u & 0x80000000u) ? ~u : (u | 0x80000000u);
}
__device__ __forceinline__ float decf(unsigned e) {
    unsigned u = (e & 0x80000000u) ? (e & 0x7fffffffu) : ~e;
    return __uint_as_float(u);
}
__device__ __forceinline__ uint32_t smem_u32(const void* p) {
    uint32_t a;
    asm("{ .reg .u64 t; cvta.to.shared.u64 t, %1; cvt.u32.u64 %0, t; }" : "=r"(a) : "l"(p));
    return a;
}
__device__ __forceinline__ void cp_async16(uint32_t saddr, const void* gaddr) {
    asm volatile("cp.async.cg.shared.global [%0], [%1], 16;" :: "r"(saddr), "l"(gaddr) : "memory");
}
__device__ __forceinline__ void ldsm_x4(uint32_t* r, uint32_t addr) {
    asm volatile("ldmatrix.sync.aligned.m8n8.x4.shared.b16 {%0,%1,%2,%3}, [%4];"
        : "=r"(r[0]), "=r"(r[1]), "=r"(r[2]), "=r"(r[3]) : "r"(addr));
}
__device__ __forceinline__ void mma_s8(int* c, const uint32_t* a, uint32_t b0, uint32_t b1) {
    asm volatile(
        "mma.sync.aligned.m16n8k32.row.col.s32.s8.s8.s32 "
        "{%0,%1,%2,%3}, {%4,%5,%6,%7}, {%8,%9}, {%0,%1,%2,%3};"
        : "+r"(c[0]), "+r"(c[1]), "+r"(c[2]), "+r"(c[3])
        : "r"(a[0]), "r"(a[1]), "r"(a[2]), "r"(a[3]), "r"(b0), "r"(b1));
}

// ---------------- prep ----------------
__global__ void maxabs_kernel(const float* __restrict__ x) {
    __shared__ float red[8];
    const float4* X4 = reinterpret_cast<const float4*>(x);
    int i = blockIdx.x * 256 + threadIdx.x;
    float m = 0.0f;
#pragma unroll
    for (int t = 0; t < 4; t++) {
        float4 v = X4[i + t * 262144];
        m = fmaxf(m, fmaxf(fmaxf(fabsf(v.x), fabsf(v.y)), fmaxf(fabsf(v.z), fabsf(v.w))));
    }
#pragma unroll
    for (int st = 16; st; st >>= 1) m = fmaxf(m, __shfl_xor_sync(~0u, m, st));
    if ((threadIdx.x & 31) == 0) red[threadIdx.x >> 5] = m;
    __syncthreads();
    if (threadIdx.x < 8) {
        m = red[threadIdx.x];
#pragma unroll
        for (int st = 4; st; st >>= 1) m = fmaxf(m, __shfl_xor_sync(0xffu, m, st));
        if (threadIdx.x == 0) atomicMax(&g_maxabs, __float_as_uint(m));
    }
}

__global__ void prep_kernel() {
    float ma = __uint_as_float(g_maxabs);
    float sc = 126.5f / ma;
    g_scale = sc;
    g_inv2 = 1.0f / (sc * sc);
}

__global__ void quant_kernel(const float* __restrict__ x) {
    int i = blockIdx.x * 256 + threadIdx.x;
    float sc = g_scale;
    float4 v = reinterpret_cast<const float4*>(x)[i];
    float q[4] = {v.x, v.y, v.z, v.w};
    uint32_t w = 0;
#pragma unroll
    for (int j = 0; j < 4; j++)
        w |= ((uint32_t)((int)rintf(q[j] * sc) & 0xff)) << (8 * j);
    reinterpret_cast<uint32_t*>(g_q)[i] = w;
}

__global__ void init_kernel() {
    int i = blockIdx.x * 256 + threadIdx.x;
    g_srow[i] = 0u; g_scol[i] = 0u;
    g_erow[i] = 0u; g_ecol[i] = 0u;
}

// ---------------- screening GEMM ----------------
__global__ __launch_bounds__(128, 2)
void gemm_screen() {
    extern __shared__ char smem[];
    const uint32_t sb = smem_u32(smem);
    const int tid = threadIdx.x;
    const int l = tid & 31, w = tid >> 5;
    const int wm = w >> 1, wn = w & 1;          // 2x2 warps, 64x64 each
    const int bx = blockIdx.x, by = blockIdx.y;

    const char* Ag = (const char*)g_q + (size_t)(by * 128) * KDIM;
    const char* Bg = (const char*)g_q + (size_t)(CNT + bx * 128) * KDIM;

#pragma unroll
    for (int i = 0; i < 16; i++) {
        int idx = tid + i * 128;
        int row = idx >> 4, c16 = idx & 15;
        uint32_t so = (uint32_t)row * TSTRIDE + c16 * 16;
        cp_async16(sb + so, Ag + row * KDIM + c16 * 16);
        cp_async16(sb + TILE_BYTES + so, Bg + row * KDIM + c16 * 16);
    }
    asm volatile("cp.async.commit_group;" ::: "memory");
    asm volatile("cp.async.wait_group 0;" ::: "memory");
    __syncthreads();

    int acc[4][8][4];   // [mt][nt][frag]
#pragma unroll
    for (int mt = 0; mt < 4; mt++)
#pragma unroll
        for (int nt = 0; nt < 8; nt++)
#pragma unroll
            for (int e = 0; e < 4; e++) acc[mt][nt][e] = 0;

    const uint32_t lrow = (uint32_t)(l & 15) * TSTRIDE + (uint32_t)(l >> 4) * 16;
    const uint32_t aBase = sb + (uint32_t)(wm * 64) * TSTRIDE + lrow;
    const uint32_t bBase = sb + TILE_BYTES + (uint32_t)(wn * 64) * TSTRIDE + lrow;

#pragma unroll
    for (int k0 = 0; k0 < KDIM; k0 += 32) {
        uint32_t af[4][4], bf[4][4];
#pragma unroll
        for (int mt = 0; mt < 4; mt++)
            ldsm_x4(af[mt], aBase + (uint32_t)(mt * 16) * TSTRIDE + k0);
#pragma unroll
        for (int np = 0; np < 4; np++)
            ldsm_x4(bf[np], bBase + (uint32_t)(np * 16) * TSTRIDE + k0);
#pragma unroll
        for (int mt = 0; mt < 4; mt++)
#pragma unroll
            for (int np = 0; np < 4; np++) {
                mma_s8(acc[mt][2 * np + 0], af[mt], bf[np][0], bf[np][2]);
                mma_s8(acc[mt][2 * np + 1], af[mt], bf[np][1], bf[np][3]);
            }
    }

    // ---- row/col maxes (regs only) ----
    const float inv2 = g_inv2;
    float rmax[8], cmax[16];
#pragma unroll
    for (int i = 0; i < 8; i++) rmax[i] = -2.0f;
#pragma unroll
    for (int i = 0; i < 16; i++) cmax[i] = -2.0f;

    const int gr0 = by * 128 + wm * 64;
    const int gc0 = bx * 128 + wn * 64;

#pragma unroll
    for (int mt = 0; mt < 4; mt++)
#pragma unroll
        for (int nt = 0; nt < 8; nt++)
#pragma unroll
            for (int h = 0; h < 2; h++) {
                int gr = gr0 + mt * 16 + (l >> 2) + 8 * h;
                int gc = gc0 + nt * 8 + 2 * (l & 3);
                float s0 = (float)acc[mt][nt][2 * h + 0] * inv2;
                float s1 = (float)acc[mt][nt][2 * h + 1] * inv2;
                float m0 = (gr == gc)     ? -2.0f : s0;
                float m1 = (gr == gc + 1) ? -2.0f : s1;
                rmax[mt * 2 + h] = fmaxf(rmax[mt * 2 + h], fmaxf(m0, m1));
                cmax[nt * 2 + 0] = fmaxf(cmax[nt * 2 + 0], m0);
                cmax[nt * 2 + 1] = fmaxf(cmax[nt * 2 + 1], m1);
            }

    // ---- stage bf16 tile in smem (reuse A region) + smem max combine ----
    unsigned* srow = reinterpret_cast<unsigned*>(smem + SM_SROW);
    unsigned* scol = reinterpret_cast<unsigned*>(smem + SM_SCOL);
    __syncthreads();               // everyone done reading A/B tiles
    srow[tid] = 0u;
    scol[tid] = 0u;
    __syncthreads();

#pragma unroll
    for (int mt = 0; mt < 4; mt++)
#pragma unroll
        for (int nt = 0; nt < 8; nt++)
#pragma unroll
            for (int h = 0; h < 2; h++) {
                int lr = wm * 64 + mt * 16 + (l >> 2) + 8 * h;
                int lc = wn * 64 + nt * 8 + 2 * (l & 3);
                __nv_bfloat162 bp;
                bp.x = __float2bfloat16_rn((float)acc[mt][nt][2 * h + 0] * inv2);
                bp.y = __float2bfloat16_rn((float)acc[mt][nt][2 * h + 1] * inv2);
                *reinterpret_cast<__nv_bfloat162*>(smem + (uint32_t)lr * TSTRIDE + lc * 2) = bp;
            }

    // warp max reductions -> smem atomics
#pragma unroll
    for (int st = 1; st <= 2; st <<= 1)
#pragma unroll
        for (int i = 0; i < 8; i++)
            rmax[i] = fmaxf(rmax[i], __shfl_xor_sync(0xffffffffu, rmax[i], st));
    if ((l & 3) == 0) {
#pragma unroll
        for (int mt = 0; mt < 4; mt++)
#pragma unroll
            for (int h = 0; h < 2; h++)
                atomicMax(&srow[wm * 64 + mt * 16 + (l >> 2) + 8 * h], encf(rmax[mt * 2 + h]));
    }
#pragma unroll
    for (int st = 4; st <= 16; st <<= 1)
#pragma unroll
        for (int i = 0; i < 16; i++)
            cmax[i] = fmaxf(cmax[i], __shfl_xor_sync(0xffffffffu, cmax[i], st));
    if (l < 4) {
#pragma unroll
        for (int nt = 0; nt < 8; nt++)
#pragma unroll
            for (int j = 0; j < 2; j++)
                atomicMax(&scol[wn * 64 + nt * 8 + 2 * l + j], encf(cmax[nt * 2 + j]));
    }
    __syncthreads();

    // coalesced dump of staged tile + global max combine
#pragma unroll
    for (int i = 0; i < 16; i++) {
        int idx = tid + i * 128;
        int row = idx >> 4, c16 = idx & 15;
        uint4 v = *reinterpret_cast<const uint4*>(smem + (uint32_t)row * TSTRIDE + c16 * 16);
        *reinterpret_cast<uint4*>(g_S + (size_t)(by * 128 + row) * CNT + bx * 128 + c16 * 8) = v;
    }
    atomicMax(&g_srow[by * 128 + tid], srow[tid]);
    atomicMax(&g_scol[bx * 128 + tid], scol[tid]);
}

// ---------------- scan + exact fix ----------------
__global__ __launch_bounds__(256)
void scan_fix(const float* __restrict__ x) {
    __shared__ float thrC[CNT];
    __shared__ unsigned list[LIST_CAP];
    __shared__ int cnt;
    const int tid = threadIdx.x;

    for (int j = tid; j < CNT; j += 256) thrC[j] = decf(g_scol[j]) - MARGIN_C;
    if (tid == 0) cnt = 0;
    __syncthreads();

    const int row0 = blockIdx.x * RPB;
    for (int r = 0; r < RPB; r++) {
        const int row = row0 + r;
        const float thrR = decf(g_srow[row]) - MARGIN_C;
        const uint4* rp = reinterpret_cast<const uint4*>(g_S + (size_t)row * CNT);
        for (int k = tid; k < CNT / 8; k += 256) {
            uint4 v = rp[k];
            unsigned wv[4] = {v.x, v.y, v.z, v.w};
            int jb = k * 8;
#pragma unroll
            for (int q2 = 0; q2 < 4; q2++) {
                __nv_bfloat162 b2 = *reinterpret_cast<__nv_bfloat162*>(&wv[q2]);
                float s0 = __bfloat162float(b2.x);
                float s1 = __bfloat162float(b2.y);
                int j0 = jb + q2 * 2, j1 = j0 + 1;
                unsigned f0 = ((s0 >= thrR) ? 2u : 0u) | ((s0 >= thrC[j0]) ? 1u : 0u);
                if (f0 && j0 != row) {
                    int id = atomicAdd(&cnt, 1);
                    if (id < LIST_CAP) list[id] = ((unsigned)j0 << 5) | ((unsigned)r << 2) | f0;
                }
                unsigned f1 = ((s1 >= thrR) ? 2u : 0u) | ((s1 >= thrC[j1]) ? 1u : 0u);
                if (f1 && j1 != row) {
                    int id = atomicAdd(&cnt, 1);
                    if (id < LIST_CAP) list[id] = ((unsigned)j1 << 5) | ((unsigned)r << 2) | f1;
                }
            }
        }
    }
    __syncthreads();

    const int m = min(cnt, LIST_CAP);
    const int wid = tid >> 5, lane = tid & 31;
    for (int e = wid; e < m; e += 8) {
        unsigned ent = list[e];
        int j = ent >> 5, r = (ent >> 2) & 7;
        int row = row0 + r;
        const float4* ap = reinterpret_cast<const float4*>(x + (size_t)row * KDIM);
        const float4* pp = reinterpret_cast<const float4*>(x + (size_t)(CNT + j) * KDIM);
        float sum = 0.0f;
#pragma unroll
        for (int t = 0; t < 2; t++) {
            float4 a = ap[lane * 2 + t], p = pp[lane * 2 + t];
            sum += a.x * p.x + a.y * p.y + a.z * p.z + a.w * p.w;
        }
#pragma unroll
        for (int st = 16; st; st >>= 1) sum += __shfl_xor_sync(~0u, sum, st);
        if (lane == 0) {
            if (ent & 2u) atomicMax(&g_erow[row], encf(sum));
            if (ent & 1u) atomicMax(&g_ecol[j], encf(sum));
        }
    }
}

__global__ void diag_kernel(const float* __restrict__ x) {
    int gw = (blockIdx.x * blockDim.x + threadIdx.x) >> 5;
    int lane = threadIdx.x & 31;
    const float4* ap = reinterpret_cast<const float4*>(x + (size_t)gw * KDIM);
    const float4* pp = reinterpret_cast<const float4*>(x + (size_t)(CNT + gw) * KDIM);
    float sum = 0.0f;
#pragma unroll
    for (int t = 0; t < 2; t++) {
        float4 a = ap[lane * 2 + t], p = pp[lane * 2 + t];
        sum += a.x * p.x + a.y * p.y + a.z * p.z + a.w * p.w;
    }
#pragma unroll
    for (int st = 16; st; st >>= 1) sum += __shfl_xor_sync(~0u, sum, st);
    if (lane == 0) g_diag[gw] = sum;
}

__global__ void finish_kernel() {
    __shared__ float red[256];
    int i = blockIdx.x * 256 + threadIdx.x;
    float smax = fmaxf(decf(g_erow[i]), decf(g_ecol[i]));
    float neg = sqrtf((1.0f - smax + EPSV) * 2.0f);
    float pos = sqrtf((1.0f - g_diag[i] + EPSV) * 2.0f);
    float t = fmaxf(1.0f - neg + pos, 0.0f);
    red[threadIdx.x] = t;
    __syncthreads();
#pragma unroll
    for (int s = 128; s > 0; s >>= 1) {
        if (threadIdx.x < s) red[threadIdx.x] += red[threadIdx.x + s];
        __syncthreads();
    }
    if (threadIdx.x == 0) g_partial[blockIdx.x] = red[0];
}

__global__ void final_kernel(float* __restrict__ out) {
    if (threadIdx.x == 0) {
        float s = 0.0f;
        for (int i = 0; i < CNT / 256; i++) s += g_partial[i];
        out[0] = s / (float)CNT;
    }
}

extern "C" void kernel_launch(void* const* d_in, const int* in_sizes, int n_in,
                              void* d_out, int out_size) {
    (void)in_sizes; (void)n_in; (void)out_size;
    const float* x = (const float*)d_in[0];
    float* out = (float*)d_out;

    cudaFuncSetAttribute((const void*)gemm_screen,
                         cudaFuncAttributeMaxDynamicSharedMemorySize, SM_TOTAL);

    maxabs_kernel<<<1024, 256>>>(x);
    prep_kernel<<<1, 1>>>();
    quant_kernel<<<2 * CNT * KDIM / 4 / 256, 256>>>(x);
    init_kernel<<<CNT / 256, 256>>>();
    dim3 grid(CNT / 128, CNT / 128);
    gemm_screen<<<grid, 128, SM_TOTAL>>>();
    scan_fix<<<CNT / RPB, 256>>>(x);
    diag_kernel<<<CNT * 32 / 256, 256>>>(x);
    finish_kernel<<<CNT / 256, 256>>>();
    final_kernel<<<1, 32>>>(out);
}

// round 7
// speedup vs baseline: 1.1597x; 1.1597x over previous
#include <cuda_runtime.h>
#include <cuda_bf16.h>
#include <cstdint>

// HardNetLoss, screen-then-fix v3:
//   R5 int8 screening GEMM (scalar LDS, 256thr, 2 CTA/SM) + staged coalesced bf16 dump,
//   vectorized fast-reject scan, exact fp32 fix, exact diagonal.

#define CNT 8192
#define KDIM 256
#define EPSV 1e-6f
#define MARGIN_C 0.05f

#define TSTRIDE 272
#define TILE_BYTES (128 * TSTRIDE)        // 34816
#define SM_SROW (2 * TILE_BYTES)
#define SM_SCOL (2 * TILE_BYTES + 512)
#define SM_TOTAL (2 * TILE_BYTES + 1024)  // 70656

#define LIST_CAP 2048
#define RPB 8

__device__ unsigned char g_q[2 * CNT * KDIM];
__device__ __nv_bfloat16 g_S[(size_t)CNT * CNT];
__device__ unsigned g_srow[CNT], g_scol[CNT];
__device__ unsigned g_erow[CNT], g_ecol[CNT];
__device__ float    g_diag[CNT];
__device__ float    g_partial[CNT / 256];
__device__ unsigned g_maxabs;

__device__ __forceinline__ unsigned encf(float f) {
    unsigned u = __float_as_uint(f);
    return (u & 0x80000000u) ? ~u : (u | 0x80000000u);
}
__device__ __forceinline__ float decf(unsigned e) {
    unsigned u = (e & 0x80000000u) ? (e & 0x7fffffffu) : ~e;
    return __uint_as_float(u);
}
__device__ __forceinline__ uint32_t smem_u32(const void* p) {
    uint32_t a;
    asm("{ .reg .u64 t; cvta.to.shared.u64 t, %1; cvt.u32.u64 %0, t; }" : "=r"(a) : "l"(p));
    return a;
}
__device__ __forceinline__ void cp_async16(uint32_t saddr, const void* gaddr) {
    asm volatile("cp.async.cg.shared.global [%0], [%1], 16;" :: "r"(saddr), "l"(gaddr) : "memory");
}
__device__ __forceinline__ void mma_s8(int* c, const uint32_t* a, const uint32_t* b) {
    asm volatile(
        "mma.sync.aligned.m16n8k32.row.col.s32.s8.s8.s32 "
        "{%0,%1,%2,%3}, {%4,%5,%6,%7}, {%8,%9}, {%0,%1,%2,%3};"
        : "+r"(c[0]), "+r"(c[1]), "+r"(c[2]), "+r"(c[3])
        : "r"(a[0]), "r"(a[1]), "r"(a[2]), "r"(a[3]), "r"(b[0]), "r"(b[1]));
}
__device__ __forceinline__ float qscale() {
    return 126.5f / __uint_as_float(g_maxabs);
}

// ---------------- prep ----------------
__global__ void maxabs_kernel(const float* __restrict__ x) {
    __shared__ float red[8];
    const float4* X4 = reinterpret_cast<const float4*>(x);
    int i = blockIdx.x * 256 + threadIdx.x;
    float m = 0.0f;
#pragma unroll
    for (int t = 0; t < 4; t++) {
        float4 v = X4[i + t * 262144];
        m = fmaxf(m, fmaxf(fmaxf(fabsf(v.x), fabsf(v.y)), fmaxf(fabsf(v.z), fabsf(v.w))));
    }
#pragma unroll
    for (int st = 16; st; st >>= 1) m = fmaxf(m, __shfl_xor_sync(~0u, m, st));
    if ((threadIdx.x & 31) == 0) red[threadIdx.x >> 5] = m;
    __syncthreads();
    if (threadIdx.x < 8) {
        m = red[threadIdx.x];
#pragma unroll
        for (int st = 4; st; st >>= 1) m = fmaxf(m, __shfl_xor_sync(0xffu, m, st));
        if (threadIdx.x == 0) atomicMax(&g_maxabs, __float_as_uint(m));
    }
}

__global__ void quant_kernel(const float* __restrict__ x) {
    int i = blockIdx.x * 256 + threadIdx.x;
    if (i < CNT) {                     // fused init of max arrays
        g_srow[i] = 0u; g_scol[i] = 0u;
        g_erow[i] = 0u; g_ecol[i] = 0u;
    }
    float sc = qscale();
    float4 v = reinterpret_cast<const float4*>(x)[i];
    float q[4] = {v.x, v.y, v.z, v.w};
    uint32_t w = 0;
#pragma unroll
    for (int j = 0; j < 4; j++)
        w |= ((uint32_t)((int)rintf(q[j] * sc) & 0xff)) << (8 * j);
    reinterpret_cast<uint32_t*>(g_q)[i] = w;
}

// ---------------- screening GEMM (R5 mainloop) ----------------
__global__ __launch_bounds__(256, 2)
void gemm_screen() {
    extern __shared__ char smem[];
    const uint32_t sb = smem_u32(smem);
    const int tid = threadIdx.x;
    const int w = tid >> 5, l = tid & 31;
    const int wm = w >> 2, wn = w & 3;
    const int bx = blockIdx.x, by = blockIdx.y;

    const char* Ag = (const char*)g_q + (size_t)(by * 128) * KDIM;
    const char* Bg = (const char*)g_q + (size_t)(CNT + bx * 128) * KDIM;

#pragma unroll
    for (int i = 0; i < 8; i++) {
        int idx = tid + i * 256;
        int row = idx >> 4, c16 = idx & 15;
        uint32_t so = (uint32_t)row * TSTRIDE + c16 * 16;
        cp_async16(sb + so, Ag + row * KDIM + c16 * 16);
        cp_async16(sb + TILE_BYTES + so, Bg + row * KDIM + c16 * 16);
    }
    asm volatile("cp.async.commit_group;" ::: "memory");
    asm volatile("cp.async.wait_group 0;" ::: "memory");
    __syncthreads();

    int acc[16][4];
#pragma unroll
    for (int t = 0; t < 16; t++)
#pragma unroll
        for (int e = 0; e < 4; e++) acc[t][e] = 0;

#pragma unroll
    for (int k0 = 0; k0 < KDIM; k0 += 32) {
        uint32_t a[4][4], b[4][2];
#pragma unroll
        for (int mt = 0; mt < 4; mt++) {
            const char* p = smem + (uint32_t)(wm * 64 + mt * 16 + (l >> 2)) * TSTRIDE
                          + k0 + (l & 3) * 4;
            a[mt][0] = *reinterpret_cast<const uint32_t*>(p);
            a[mt][1] = *reinterpret_cast<const uint32_t*>(p + 8 * TSTRIDE);
            a[mt][2] = *reinterpret_cast<const uint32_t*>(p + 16);
            a[mt][3] = *reinterpret_cast<const uint32_t*>(p + 8 * TSTRIDE + 16);
        }
#pragma unroll
        for (int nt = 0; nt < 4; nt++) {
            const char* p = smem + TILE_BYTES + (uint32_t)(wn * 32 + nt * 8 + (l >> 2)) * TSTRIDE
                          + k0 + (l & 3) * 4;
            b[nt][0] = *reinterpret_cast<const uint32_t*>(p);
            b[nt][1] = *reinterpret_cast<const uint32_t*>(p + 16);
        }
#pragma unroll
        for (int mt = 0; mt < 4; mt++)
#pragma unroll
            for (int nt = 0; nt < 4; nt++)
                mma_s8(acc[mt * 4 + nt], a[mt], b[nt]);
    }

    // ---- epilogue: maxes in regs, stage bf16 tile into A smem, coalesced dump ----
    unsigned* srow = reinterpret_cast<unsigned*>(smem + SM_SROW);
    unsigned* scol = reinterpret_cast<unsigned*>(smem + SM_SCOL);
    const float inv2 = 1.0f / (qscale() * qscale());

    float rmax[8], cmax[8];
#pragma unroll
    for (int i = 0; i < 8; i++) { rmax[i] = -2.0f; cmax[i] = -2.0f; }

    __syncthreads();               // done reading A/B tiles
    if (tid < 128) srow[tid] = 0u; else scol[tid - 128] = 0u;
    __syncthreads();

#pragma unroll
    for (int mt = 0; mt < 4; mt++)
#pragma unroll
        for (int nt = 0; nt < 4; nt++)
#pragma unroll
            for (int h = 0; h < 2; h++) {
                int lr = wm * 64 + mt * 16 + (l >> 2) + h * 8;
                int lc = wn * 32 + nt * 8 + 2 * (l & 3);
                float s0 = (float)acc[mt * 4 + nt][2 * h + 0] * inv2;
                float s1 = (float)acc[mt * 4 + nt][2 * h + 1] * inv2;
                __nv_bfloat162 bp;
                bp.x = __float2bfloat16_rn(s0);
                bp.y = __float2bfloat16_rn(s1);
                *reinterpret_cast<__nv_bfloat162*>(smem + (uint32_t)lr * TSTRIDE + lc * 2) = bp;
                if (by * 128 + lr == bx * 128 + lc) s0 = -2.0f;
                if (by * 128 + lr == bx * 128 + lc + 1) s1 = -2.0f;
                rmax[mt * 2 + h] = fmaxf(rmax[mt * 2 + h], fmaxf(s0, s1));
                cmax[nt * 2 + 0] = fmaxf(cmax[nt * 2 + 0], s0);
                cmax[nt * 2 + 1] = fmaxf(cmax[nt * 2 + 1], s1);
            }

#pragma unroll
    for (int st = 1; st <= 2; st <<= 1)
#pragma unroll
        for (int i = 0; i < 8; i++)
            rmax[i] = fmaxf(rmax[i], __shfl_xor_sync(0xffffffffu, rmax[i], st));
    if ((l & 3) == 0) {
#pragma unroll
        for (int mt = 0; mt < 4; mt++)
#pragma unroll
            for (int h = 0; h < 2; h++)
                atomicMax(&srow[wm * 64 + mt * 16 + (l >> 2) + h * 8], encf(rmax[mt * 2 + h]));
    }
#pragma unroll
    for (int st = 4; st <= 16; st <<= 1)
#pragma unroll
        for (int i = 0; i < 8; i++)
            cmax[i] = fmaxf(cmax[i], __shfl_xor_sync(0xffffffffu, cmax[i], st));
    if (l < 4) {
#pragma unroll
        for (int nt = 0; nt < 4; nt++)
#pragma unroll
            for (int j = 0; j < 2; j++)
                atomicMax(&scol[wn * 32 + nt * 8 + 2 * l + j], encf(cmax[nt * 2 + j]));
    }
    __syncthreads();

    // coalesced 16B dump of staged tile + global max combine
#pragma unroll
    for (int i = 0; i < 8; i++) {
        int idx = tid + i * 256;
        int row = idx >> 4, c16 = idx & 15;
        uint4 v = *reinterpret_cast<const uint4*>(smem + (uint32_t)row * TSTRIDE + c16 * 16);
        *reinterpret_cast<uint4*>(g_S + (size_t)(by * 128 + row) * CNT + bx * 128 + c16 * 8) = v;
    }
    if (tid < 128) atomicMax(&g_srow[by * 128 + tid], srow[tid]);
    else           atomicMax(&g_scol[bx * 128 + tid - 128], scol[tid - 128]);
}

// ---------------- scan + exact fix ----------------
__global__ __launch_bounds__(256)
void scan_fix(const float* __restrict__ x) {
    __shared__ float thrC[CNT];          // 32 KB
    __shared__ float minThr8[CNT / 8];   // 4 KB
    __shared__ unsigned list[LIST_CAP];  // 8 KB
    __shared__ int cnt;
    const int tid = threadIdx.x;

    for (int j = tid; j < CNT; j += 256) thrC[j] = decf(g_scol[j]) - MARGIN_C;
    if (tid == 0) cnt = 0;
    __syncthreads();
    for (int g = tid; g < CNT / 8; g += 256) {
        float m = thrC[g * 8];
#pragma unroll
        for (int t = 1; t < 8; t++) m = fminf(m, thrC[g * 8 + t]);
        minThr8[g] = m;
    }
    __syncthreads();

    const int row0 = blockIdx.x * RPB;
    for (int r = 0; r < RPB; r++) {
        const int row = row0 + r;
        const float thrR = decf(g_srow[row]) - MARGIN_C;
        const uint4* rp = reinterpret_cast<const uint4*>(g_S + (size_t)row * CNT);
        for (int k = tid; k < CNT / 8; k += 256) {
            uint4 v = rp[k];
            __nv_bfloat162 p0 = *reinterpret_cast<__nv_bfloat162*>(&v.x);
            __nv_bfloat162 p1 = *reinterpret_cast<__nv_bfloat162*>(&v.y);
            __nv_bfloat162 p2 = *reinterpret_cast<__nv_bfloat162*>(&v.z);
            __nv_bfloat162 p3 = *reinterpret_cast<__nv_bfloat162*>(&v.w);
            __nv_bfloat162 mm = __hmax2(__hmax2(p0, p1), __hmax2(p2, p3));
            float vmax = fmaxf(__low2float(mm), __high2float(mm));
            if (vmax < thrR && vmax < minThr8[k]) continue;   // fast reject
            unsigned wv[4] = {v.x, v.y, v.z, v.w};
            int jb = k * 8;
#pragma unroll
            for (int q2 = 0; q2 < 4; q2++) {
                __nv_bfloat162 b2 = *reinterpret_cast<__nv_bfloat162*>(&wv[q2]);
                float s0 = __bfloat162float(b2.x);
                float s1 = __bfloat162float(b2.y);
                int j0 = jb + q2 * 2, j1 = j0 + 1;
                unsigned f0 = ((s0 >= thrR) ? 2u : 0u) | ((s0 >= thrC[j0]) ? 1u : 0u);
                if (f0 && j0 != row) {
                    int id = atomicAdd(&cnt, 1);
                    if (id < LIST_CAP) list[id] = ((unsigned)j0 << 5) | ((unsigned)r << 2) | f0;
                }
                unsigned f1 = ((s1 >= thrR) ? 2u : 0u) | ((s1 >= thrC[j1]) ? 1u : 0u);
                if (f1 && j1 != row) {
                    int id = atomicAdd(&cnt, 1);
                    if (id < LIST_CAP) list[id] = ((unsigned)j1 << 5) | ((unsigned)r << 2) | f1;
                }
            }
        }
    }
    __syncthreads();

    const int m = min(cnt, LIST_CAP);
    const int wid = tid >> 5, lane = tid & 31;
    for (int e = wid; e < m; e += 8) {
        unsigned ent = list[e];
        int j = ent >> 5, r = (ent >> 2) & 7;
        int row = row0 + r;
        const float4* ap = reinterpret_cast<const float4*>(x + (size_t)row * KDIM);
        const float4* pp = reinterpret_cast<const float4*>(x + (size_t)(CNT + j) * KDIM);
        float sum = 0.0f;
#pragma unroll
        for (int t = 0; t < 2; t++) {
            float4 a = ap[lane * 2 + t], p = pp[lane * 2 + t];
            sum += a.x * p.x + a.y * p.y + a.z * p.z + a.w * p.w;
        }
#pragma unroll
        for (int st = 16; st; st >>= 1) sum += __shfl_xor_sync(~0u, sum, st);
        if (lane == 0) {
            if (ent & 2u) atomicMax(&g_erow[row], encf(sum));
            if (ent & 1u) atomicMax(&g_ecol[j], encf(sum));
        }
    }
}

__global__ void diag_kernel(const float* __restrict__ x) {
    int gw = (blockIdx.x * blockDim.x + threadIdx.x) >> 5;
    int lane = threadIdx.x & 31;
    const float4* ap = reinterpret_cast<const float4*>(x + (size_t)gw * KDIM);
    const float4* pp = reinterpret_cast<const float4*>(x + (size_t)(CNT + gw) * KDIM);
    float sum = 0.0f;
#pragma unroll
    for (int t = 0; t < 2; t++) {
        float4 a = ap[lane * 2 + t], p = pp[lane * 2 + t];
        sum += a.x * p.x + a.y * p.y + a.z * p.z + a.w * p.w;
    }
#pragma unroll
    for (int st = 16; st; st >>= 1) sum += __shfl_xor_sync(~0u, sum, st);
    if (lane == 0) g_diag[gw] = sum;
}

__global__ void finish_kernel() {
    __shared__ float red[256];
    int i = blockIdx.x * 256 + threadIdx.x;
    float smax = fmaxf(decf(g_erow[i]), decf(g_ecol[i]));
    float neg = sqrtf((1.0f - smax + EPSV) * 2.0f);
    float pos = sqrtf((1.0f - g_diag[i] + EPSV) * 2.0f);
    float t = fmaxf(1.0f - neg + pos, 0.0f);
    red[threadIdx.x] = t;
    __syncthreads();
#pragma unroll
    for (int s = 128; s > 0; s >>= 1) {
        if (threadIdx.x < s) red[threadIdx.x] += red[threadIdx.x + s];
        __syncthreads();
    }
    if (threadIdx.x == 0) g_partial[blockIdx.x] = red[0];
}

__global__ void final_kernel(float* __restrict__ out) {
    if (threadIdx.x == 0) {
        float s = 0.0f;
        for (int i = 0; i < CNT / 256; i++) s += g_partial[i];
        out[0] = s / (float)CNT;
    }
}

extern "C" void kernel_launch(void* const* d_in, const int* in_sizes, int n_in,
                              void* d_out, int out_size) {
    (void)in_sizes; (void)n_in; (void)out_size;
    const float* x = (const float*)d_in[0];
    float* out = (float*)d_out;

    cudaFuncSetAttribute((const void*)gemm_screen,
                         cudaFuncAttributeMaxDynamicSharedMemorySize, SM_TOTAL);

    maxabs_kernel<<<1024, 256>>>(x);
    quant_kernel<<<2 * CNT * KDIM / 4 / 256, 256>>>(x);
    dim3 grid(CNT / 128, CNT / 128);
    gemm_screen<<<grid, 256, SM_TOTAL>>>();
    scan_fix<<<CNT / RPB, 256>>>(x);
    diag_kernel<<<CNT * 32 / 256, 256>>>(x);
    finish_kernel<<<CNT / 256, 256>>>();
    final_kernel<<<1, 32>>>(out);
}